// round 8
// baseline (speedup 1.0000x reference)
#include <cuda_runtime.h>
#include <cuda_bf16.h>
#include <math.h>
#include <stdint.h>

// Problem constants
#define SQ   2048
#define HID  1024
#define DH   64
#define NHB  16          // b*8+h combos per branch (B=2, 8 heads)
#define BHSD (NHB*SQ*DH)

// ---------------- scratch (static device memory; no allocation) ----------------
__device__ float g_Q   [BHSD];
__device__ float g_V   [BHSD];      // tf32-rounded at write
__device__ float g_LQ  [BHSD];
__device__ float g_LK1 [BHSD];
__device__ float g_LV  [BHSD];      // tf32-rounded at write
__device__ float g_LQ2 [BHSD];
__device__ float g_K2  [2*BHSD];    // packed (hi,lo) per element
__device__ float g_LK22[2*BHSD];    // packed (hi,lo) per element
__device__ float g_Mm  [NHB*64*64];
__device__ float g_wsum[HID*512];
__device__ float g_bsum[512];

struct ProjW {
    const float* w[7];
    const float* b[7];
};

// ---------------- tf32 helpers ----------------
__device__ __forceinline__ float tf32_rna(float x) {
    uint32_t r; asm("cvt.rna.tf32.f32 %0, %1;" : "=r"(r) : "f"(x));
    return __uint_as_float(r);
}

// mma.m16n8k8 row.col tf32, fp32 accumulate (in-place)
__device__ __forceinline__ void mma8(float c[4],
        float a0, float a1, float a2, float a3, float b0, float b1) {
    uint32_t A0 = __float_as_uint(a0), A1 = __float_as_uint(a1),
             A2 = __float_as_uint(a2), A3 = __float_as_uint(a3),
             B0 = __float_as_uint(b0), B1 = __float_as_uint(b1);
    asm volatile(
        "mma.sync.aligned.m16n8k8.row.col.f32.tf32.tf32.f32 "
        "{%0,%1,%2,%3}, {%4,%5,%6,%7}, {%8,%9}, {%0,%1,%2,%3};"
        : "+f"(c[0]), "+f"(c[1]), "+f"(c[2]), "+f"(c[3])
        : "r"(A0), "r"(A1), "r"(A2), "r"(A3), "r"(B0), "r"(B1));
}

__device__ __forceinline__ void cp16(uint32_t dst, const float* src) {
    asm volatile("cp.async.cg.shared.global [%0], [%1], 16;\n" :: "r"(dst), "l"(src));
}

// ---------------- kernel 0: fold wlv1+wlv2 ----------------
__global__ void sum_lv_weights(const float* __restrict__ w1, const float* __restrict__ w2,
                               const float* __restrict__ b1, const float* __restrict__ b2) {
    int i = blockIdx.x * blockDim.x + threadIdx.x;
    if (i < HID*512) g_wsum[i] = w1[i] + w2[i];
    if (i < 512)     g_bsum[i] = b1[i] + b2[i];
}

// ---------------- kernel 1: projection GEMM (3xTF32 tensor-core) ----------------
// Out = X @ W + bias.  M=4096, N=512, K=1024, 7 projections.
// pz: 0=Q raw, 1=K packed-split, 2=V tf32-rounded, 3=LQ raw, 4=LK1 raw,
//     5=LK2 packed-split, 6=LV tf32-rounded (uses g_wsum/g_bsum)
#define XS_STRIDE 18    // float2 units (16 + 2 pad)
#define WS_STRIDE 132   // float2 units (128 + 4 pad)

__global__ __launch_bounds__(256) void proj_tc(const float* __restrict__ X, ProjW args) {
    const int pz = blockIdx.z;
    const float* __restrict__ W  = (pz == 6) ? g_wsum : args.w[pz];
    const float* __restrict__ Bv = (pz == 6) ? g_bsum : args.b[pz];

    float* Out = nullptr;      // raw / rounded targets
    float2* Out2 = nullptr;    // packed targets
    switch (pz) {
        case 0: Out = g_Q;   break;
        case 1: Out2 = (float2*)g_K2; break;
        case 2: Out = g_V;   break;
        case 3: Out = g_LQ;  break;
        case 4: Out = g_LK1; break;
        case 5: Out2 = (float2*)g_LK22; break;
        case 6: Out = g_LV;  break;
    }
    const bool roundV = (pz == 2 || pz == 6);

    const int n0 = blockIdx.x * 128;
    const int m0 = blockIdx.y * 128;

    __shared__ float2 Xs[128 * XS_STRIDE];
    __shared__ float2 Ws[16 * WS_STRIDE];

    const int tid  = threadIdx.x;
    const int w    = tid >> 5;
    const int lane = tid & 31;
    const int g    = lane >> 2;
    const int tg   = lane & 3;
    const int wm   = w & 3;        // row group: rows 32*wm
    const int wn   = w >> 2;       // col group: cols 64*wn

    float acc[2][8][4];
    #pragma unroll
    for (int mt = 0; mt < 2; mt++)
        #pragma unroll
        for (int n = 0; n < 8; n++)
            #pragma unroll
            for (int q = 0; q < 4; q++) acc[mt][n][q] = 0.f;

    float4 xr[2], wr[2];
    auto loadX = [&](int kb) {
        #pragma unroll
        for (int t = 0; t < 2; t++) {
            int i2 = tid + 256*t; int r = i2 >> 2, c = i2 & 3;
            xr[t] = *(const float4*)&X[(size_t)(m0 + r) * HID + kb + 4*c];
        }
    };
    auto loadW = [&](int kb) {
        #pragma unroll
        for (int t = 0; t < 2; t++) {
            int i2 = tid + 256*t; int r = i2 >> 5, c = i2 & 31;
            wr[t] = *(const float4*)&W[(size_t)(kb + r) * 512 + n0 + 4*c];
        }
    };

    loadX(0); loadW(0);

    for (int kb = 0; kb < HID; kb += 16) {
        __syncthreads();
        #pragma unroll
        for (int t = 0; t < 2; t++) {
            int i2 = tid + 256*t; int r = i2 >> 2, c = i2 & 3;
            float4 x = xr[t];
            float h0 = tf32_rna(x.x), h1 = tf32_rna(x.y), h2 = tf32_rna(x.z), h3 = tf32_rna(x.w);
            float4* p = (float4*)&Xs[r * XS_STRIDE + 4*c];
            p[0] = make_float4(h0, x.x - h0, h1, x.y - h1);
            p[1] = make_float4(h2, x.z - h2, h3, x.w - h3);
        }
        #pragma unroll
        for (int t = 0; t < 2; t++) {
            int i2 = tid + 256*t; int r = i2 >> 5, c = i2 & 31;
            float4 x = wr[t];
            float h0 = tf32_rna(x.x), h1 = tf32_rna(x.y), h2 = tf32_rna(x.z), h3 = tf32_rna(x.w);
            float4* p = (float4*)&Ws[r * WS_STRIDE + 4*c];
            p[0] = make_float4(h0, x.x - h0, h1, x.y - h1);
            p[1] = make_float4(h2, x.z - h2, h3, x.w - h3);
        }
        if (kb + 16 < HID) { loadX(kb + 16); loadW(kb + 16); }
        __syncthreads();

        #pragma unroll
        for (int kk = 0; kk < 2; kk++) {
            float2 a[2][4];
            #pragma unroll
            for (int mt = 0; mt < 2; mt++) {
                int r = 32*wm + 16*mt;
                a[mt][0] = Xs[(r + g    ) * XS_STRIDE + 8*kk + tg    ];
                a[mt][1] = Xs[(r + g + 8) * XS_STRIDE + 8*kk + tg    ];
                a[mt][2] = Xs[(r + g    ) * XS_STRIDE + 8*kk + tg + 4];
                a[mt][3] = Xs[(r + g + 8) * XS_STRIDE + 8*kk + tg + 4];
            }
            #pragma unroll
            for (int n = 0; n < 8; n++) {
                float2 b0 = Ws[(8*kk + tg    ) * WS_STRIDE + 64*wn + 8*n + g];
                float2 b1 = Ws[(8*kk + tg + 4) * WS_STRIDE + 64*wn + 8*n + g];
                #pragma unroll
                for (int mt = 0; mt < 2; mt++) {
                    mma8(acc[mt][n], a[mt][0].x, a[mt][1].x, a[mt][2].x, a[mt][3].x, b0.x, b1.x);
                    mma8(acc[mt][n], a[mt][0].x, a[mt][1].x, a[mt][2].x, a[mt][3].x, b0.y, b1.y);
                    mma8(acc[mt][n], a[mt][0].y, a[mt][1].y, a[mt][2].y, a[mt][3].y, b0.x, b1.x);
                }
            }
        }
    }

    // epilogue: bias + scatter to [bh][s][d], format depends on pz
    #pragma unroll
    for (int mt = 0; mt < 2; mt++) {
        #pragma unroll
        for (int n = 0; n < 8; n++) {
            int col = 64*wn + 8*n + 2*tg;   // 0..127 within block
            int hh  = (n0 + col) >> 6;      // head
            int d   = (n0 + col) & 63;
            float b0 = Bv[n0 + col], b1 = Bv[n0 + col + 1];
            #pragma unroll
            for (int half = 0; half < 2; half++) {
                int m = m0 + 32*wm + 16*mt + g + 8*half;
                int bb = m >> 11, s = m & 2047;
                float v0 = acc[mt][n][2*half + 0] + b0;
                float v1 = acc[mt][n][2*half + 1] + b1;
                size_t base = (size_t)((bb*8 + hh) * SQ + s) * DH + d;
                if (Out2) {
                    float h0 = tf32_rna(v0), h1 = tf32_rna(v1);
                    *(float4*)&Out2[base] = make_float4(h0, v0 - h0, h1, v1 - h1);
                } else if (roundV) {
                    *(float2*)&Out[base] = make_float2(tf32_rna(v0), tf32_rna(v1));
                } else {
                    *(float2*)&Out[base] = make_float2(v0, v1);
                }
            }
        }
    }
}

// ---------------- kernel 2: Gram matrix G = LK1^T LK1 per (b,h) (fp32) ----------------
__global__ __launch_bounds__(256) void gram_kernel() {
    const int bh = blockIdx.x;
    const float* __restrict__ P = g_LK1 + (size_t)bh * SQ * DH;
    __shared__ float T[32][65];
    const int tid = threadIdx.x;
    const int ty = tid >> 4, tx = tid & 15;

    float acc[4][4];
    #pragma unroll
    for (int i = 0; i < 4; i++)
        #pragma unroll
        for (int j = 0; j < 4; j++) acc[i][j] = 0.f;

    for (int s0 = 0; s0 < SQ; s0 += 32) {
        #pragma unroll
        for (int t = 0; t < 2; t++) {
            int idx = tid + t * 256;
            int r = idx >> 4, c = idx & 15;
            float4 v = *(const float4*)&P[(size_t)(s0 + r) * DH + 4*c];
            T[r][4*c+0] = v.x; T[r][4*c+1] = v.y; T[r][4*c+2] = v.z; T[r][4*c+3] = v.w;
        }
        __syncthreads();
        #pragma unroll 8
        for (int ss = 0; ss < 32; ss++) {
            float a_[4], b_[4];
            #pragma unroll
            for (int i = 0; i < 4; i++) a_[i] = T[ss][4*ty + i];
            #pragma unroll
            for (int j = 0; j < 4; j++) b_[j] = T[ss][4*tx + j];
            #pragma unroll
            for (int i = 0; i < 4; i++)
                #pragma unroll
                for (int j = 0; j < 4; j++) acc[i][j] += a_[i] * b_[j];
        }
        __syncthreads();
    }
    #pragma unroll
    for (int i = 0; i < 4; i++)
        #pragma unroll
        for (int j = 0; j < 4; j++)
            g_Mm[bh*4096 + (4*ty + i)*64 + (4*tx + j)] = acc[i][j];
}

// ---------------- kernel 3: LQ2 = (LQ @ G) * scale (fp32) ----------------
__global__ __launch_bounds__(256) void lqx_kernel() {
    const int bh = blockIdx.y;
    const int r0 = blockIdx.x * 64;
    const float* __restrict__ Qp = g_LQ + (size_t)bh * SQ * DH;
    const float* __restrict__ Mp = g_Mm + bh * 4096;

    __shared__ float Msm[64*65];
    __shared__ float Qt[64*65];

    const int tid = threadIdx.x;
    const int ty = tid >> 4, tx = tid & 15;

    #pragma unroll
    for (int t = 0; t < 4; t++) {
        int idx = tid + t * 256;
        int r = idx >> 4, c = idx & 15;
        float4 mv = *(const float4*)&Mp[r*64 + 4*c];
        Msm[r*65 + 4*c+0] = mv.x; Msm[r*65 + 4*c+1] = mv.y;
        Msm[r*65 + 4*c+2] = mv.z; Msm[r*65 + 4*c+3] = mv.w;
        float4 qv = *(const float4*)&Qp[(size_t)(r0 + r) * DH + 4*c];
        Qt[r*65 + 4*c+0] = qv.x; Qt[r*65 + 4*c+1] = qv.y;
        Qt[r*65 + 4*c+2] = qv.z; Qt[r*65 + 4*c+3] = qv.w;
    }
    __syncthreads();

    float acc[4][4];
    #pragma unroll
    for (int a = 0; a < 4; a++)
        #pragma unroll
        for (int b = 0; b < 4; b++) acc[a][b] = 0.f;

    #pragma unroll 4
    for (int k = 0; k < 64; k++) {
        float qa[4], mb[4];
        #pragma unroll
        for (int a = 0; a < 4; a++) qa[a] = Qt[(ty + 16*a)*65 + k];
        #pragma unroll
        for (int b = 0; b < 4; b++) mb[b] = Msm[k*65 + tx + 16*b];
        #pragma unroll
        for (int a = 0; a < 4; a++)
            #pragma unroll
            for (int b = 0; b < 4; b++) acc[a][b] += qa[a] * mb[b];
    }

    const float scale = 0.125f;  // 1/sqrt(64)
    #pragma unroll
    for (int a = 0; a < 4; a++)
        #pragma unroll
        for (int b = 0; b < 4; b++)
            g_LQ2[(size_t)bh * SQ * DH + (size_t)(r0 + ty + 16*a) * DH + tx + 16*b]
                = acc[a][b] * scale;
}

// ---------------- kernel 4: flash attention, pre-split K + pre-rounded V ----------------
// BR=64, BC=64, 128 threads = 4 warps. K packed (hi,lo) float2 staged via cp.async
// (stride 68 float2), V tf32-rounded fp32 (stride 72). QK 3-term, PV exact 2-term.
#define KS2 68   // float2 stride for packed K rows
#define VS2 72   // float stride for V rows

__global__ __launch_bounds__(128, 2) void flash_tc3(const float* __restrict__ mask,
                                                    float* __restrict__ out) {
    extern __shared__ float fsm[];
    float2* Kb0 = (float2*)fsm;                    // 64*KS2 float2
    float2* Kb1 = Kb0 + 64*KS2;
    float*  Vb0 = (float*)(Kb1 + 64*KS2);          // 64*VS2 float
    float*  Vb1 = Vb0 + 64*VS2;

    const int rt = blockIdx.x;
    const int hb = blockIdx.y;
    const int branch = hb >> 4;
    const int cidx = hb & 15;
    const int bb = cidx >> 3;
    const int h  = cidx & 7;

    const float* Qp; const float2* Kp2; const float* Vp;
    float qscale; int ho;
    bool domask = false;
    if (branch == 0) {
        Qp  = g_Q + (size_t)cidx * SQ * DH;
        Kp2 = (const float2*)g_K2 + (size_t)cidx * SQ * DH;
        Vp  = g_V + (size_t)cidx * SQ * DH;
        qscale = 0.125f; ho = h; domask = true;
    } else {
        Qp  = g_LQ2 + (size_t)cidx * SQ * DH;
        Kp2 = (const float2*)g_LK22 + (size_t)cidx * SQ * DH;
        Vp  = g_LV + (size_t)cidx * SQ * DH;
        qscale = 1.0f; ho = 8 + h;
    }

    const int tid  = threadIdx.x;
    const int lane = tid & 31;
    const int g    = lane >> 2;
    const int tg   = lane & 3;
    const int r0   = 16 * (tid >> 5);

    const uint32_t kb0 = (uint32_t)__cvta_generic_to_shared(Kb0);
    const uint32_t kb1 = (uint32_t)__cvta_generic_to_shared(Kb1);
    const uint32_t vb0 = (uint32_t)__cvta_generic_to_shared(Vb0);
    const uint32_t vb1 = (uint32_t)__cvta_generic_to_shared(Vb1);

    auto stage = [&](int kt, int buf) {
        uint32_t kb = buf ? kb1 : kb0;
        uint32_t vb = buf ? vb1 : vb0;
        // K packed: 64 rows x 64 float2 = 2048 x 16B
        #pragma unroll
        for (int t = 0; t < 16; t++) {
            int idx = tid + 128*t;
            int r = idx >> 5, c = idx & 31;
            cp16(kb + (uint32_t)(r*KS2 + 2*c)*8u,
                 (const float*)(Kp2 + (size_t)(kt*64 + r) * DH + 2*c));
        }
        // V: 64 rows x 64 float = 1024 x 16B
        #pragma unroll
        for (int t = 0; t < 8; t++) {
            int idx = tid + 128*t;
            int r = idx >> 4, c = idx & 15;
            cp16(vb + (uint32_t)(r*VS2 + 4*c)*4u,
                 &Vp[(size_t)(kt*64 + r) * DH + 4*c]);
        }
        asm volatile("cp.async.commit_group;\n");
    };

    // ---- Q fragments, raw fp32 scaled (register-resident; split at use) ----
    float qf[8][4];
    {
        const float* qbase = Qp + (size_t)(rt*64) * DH;
        #pragma unroll
        for (int kk = 0; kk < 8; kk++) {
            qf[kk][0] = qbase[(size_t)(r0 + g    ) * DH + 8*kk + tg    ] * qscale;
            qf[kk][1] = qbase[(size_t)(r0 + g + 8) * DH + 8*kk + tg    ] * qscale;
            qf[kk][2] = qbase[(size_t)(r0 + g    ) * DH + 8*kk + tg + 4] * qscale;
            qf[kk][3] = qbase[(size_t)(r0 + g + 8) * DH + 8*kk + tg + 4] * qscale;
        }
    }

    float o[8][4];
    #pragma unroll
    for (int n = 0; n < 8; n++)
        #pragma unroll
        for (int q = 0; q < 4; q++) o[n][q] = 0.f;
    float m0r = -3.0e38f, m1r = -3.0e38f, l0r = 0.f, l1r = 0.f;

    stage(0, 0);

    for (int kt = 0; kt < 32; kt++) {
        if (kt + 1 < 32) {
            stage(kt + 1, (kt + 1) & 1);
            asm volatile("cp.async.wait_group 1;\n");
        } else {
            asm volatile("cp.async.wait_group 0;\n");
        }
        __syncthreads();
        const float2* Ks = (kt & 1) ? Kb1 : Kb0;
        const float*  Vs = (kt & 1) ? Vb1 : Vb0;

        // ---- S = Q K^T (3-term: Qhi*Khi + Qhi*Klo + Qlo*Khi) ----
        float sv[8][4];
        #pragma unroll
        for (int n = 0; n < 8; n++)
            #pragma unroll
            for (int q = 0; q < 4; q++) sv[n][q] = 0.f;

        #pragma unroll
        for (int kk = 0; kk < 8; kk++) {
            float qh[4], ql[4];
            #pragma unroll
            for (int i = 0; i < 4; i++) {
                qh[i] = tf32_rna(qf[kk][i]);
                ql[i] = qf[kk][i] - qh[i];
            }
            #pragma unroll
            for (int n = 0; n < 8; n++) {
                float2 b0 = Ks[(8*n + g) * KS2 + 8*kk + tg    ];
                float2 b1 = Ks[(8*n + g) * KS2 + 8*kk + tg + 4];
                mma8(sv[n], qh[0], qh[1], qh[2], qh[3], b0.x, b1.x);
                mma8(sv[n], qh[0], qh[1], qh[2], qh[3], b0.y, b1.y);
                mma8(sv[n], ql[0], ql[1], ql[2], ql[3], b0.x, b1.x);
            }
        }

        if (domask) {
            #pragma unroll
            for (int n = 0; n < 8; n++) {
                float2 mm = __ldg((const float2*)&mask[(size_t)bb * SQ + kt*64 + 8*n + 2*tg]);
                sv[n][0] += mm.x; sv[n][1] += mm.y;
                sv[n][2] += mm.x; sv[n][3] += mm.y;
            }
        }

        // ---- online softmax (rows g and g+8; 4-lane groups share a row) ----
        float mt0 = sv[0][0], mt1 = sv[0][2];
        #pragma unroll
        for (int n = 0; n < 8; n++) {
            mt0 = fmaxf(mt0, fmaxf(sv[n][0], sv[n][1]));
            mt1 = fmaxf(mt1, fmaxf(sv[n][2], sv[n][3]));
        }
        mt0 = fmaxf(mt0, __shfl_xor_sync(0xffffffffu, mt0, 1));
        mt0 = fmaxf(mt0, __shfl_xor_sync(0xffffffffu, mt0, 2));
        mt1 = fmaxf(mt1, __shfl_xor_sync(0xffffffffu, mt1, 1));
        mt1 = fmaxf(mt1, __shfl_xor_sync(0xffffffffu, mt1, 2));

        float mn0 = fmaxf(m0r, mt0), mn1 = fmaxf(m1r, mt1);
        float c0 = __expf(m0r - mn0), c1 = __expf(m1r - mn1);
        float s0 = 0.f, s1 = 0.f;
        #pragma unroll
        for (int n = 0; n < 8; n++) {
            sv[n][0] = __expf(sv[n][0] - mn0); s0 += sv[n][0];
            sv[n][1] = __expf(sv[n][1] - mn0); s0 += sv[n][1];
            sv[n][2] = __expf(sv[n][2] - mn1); s1 += sv[n][2];
            sv[n][3] = __expf(sv[n][3] - mn1); s1 += sv[n][3];
        }
        s0 += __shfl_xor_sync(0xffffffffu, s0, 1);
        s0 += __shfl_xor_sync(0xffffffffu, s0, 2);
        s1 += __shfl_xor_sync(0xffffffffu, s1, 1);
        s1 += __shfl_xor_sync(0xffffffffu, s1, 2);
        l0r = l0r * c0 + s0; m0r = mn0;
        l1r = l1r * c1 + s1; m1r = mn1;
        #pragma unroll
        for (int n = 0; n < 8; n++) {
            o[n][0] *= c0; o[n][1] *= c0;
            o[n][2] *= c1; o[n][3] *= c1;
        }

        // ---- O += P V: shfl C->A layout, exact 2-term (Phi+Plo)*Vtf32 ----
        const int src0 = (lane & ~3) | (tg >> 1);
        const int src2 = src0 + 2;
        const bool odd = (tg & 1);
        #pragma unroll
        for (int kk = 0; kk < 8; kk++) {
            float p00 = __shfl_sync(0xffffffffu, sv[kk][0], src0);
            float p01 = __shfl_sync(0xffffffffu, sv[kk][1], src0);
            float p20 = __shfl_sync(0xffffffffu, sv[kk][2], src0);
            float p21 = __shfl_sync(0xffffffffu, sv[kk][3], src0);
            float q00 = __shfl_sync(0xffffffffu, sv[kk][0], src2);
            float q01 = __shfl_sync(0xffffffffu, sv[kk][1], src2);
            float q20 = __shfl_sync(0xffffffffu, sv[kk][2], src2);
            float q21 = __shfl_sync(0xffffffffu, sv[kk][3], src2);
            float a0 = odd ? p01 : p00;   // P[g   ][8kk+tg]
            float a1 = odd ? p21 : p20;   // P[g+8 ][8kk+tg]
            float a2 = odd ? q01 : q00;   // P[g   ][8kk+tg+4]
            float a3 = odd ? q21 : q20;   // P[g+8 ][8kk+tg+4]
            float ah0 = tf32_rna(a0), al0 = a0 - ah0;
            float ah1 = tf32_rna(a1), al1 = a1 - ah1;
            float ah2 = tf32_rna(a2), al2 = a2 - ah2;
            float ah3 = tf32_rna(a3), al3 = a3 - ah3;
            #pragma unroll
            for (int n = 0; n < 8; n++) {
                float b0 = Vs[(8*kk + tg    ) * VS2 + 8*n + g];
                float b1 = Vs[(8*kk + tg + 4) * VS2 + 8*n + g];
                mma8(o[n], ah0, ah1, ah2, ah3, b0, b1);
                mma8(o[n], al0, al1, al2, al3, b0, b1);
            }
        }
        __syncthreads();   // all warps done reading this buffer before re-staging
    }

    // ---- epilogue ----
    float inv0 = 1.0f / l0r, inv1 = 1.0f / l1r;
    int s0row = rt*64 + r0 + g;
    int s1row = s0row + 8;
    #pragma unroll
    for (int n = 0; n < 8; n++) {
        int col = 8*n + 2*tg;
        *(float2*)&out[(size_t)(bb * SQ + s0row) * HID + ho*64 + col] =
            make_float2(o[n][0] * inv0, o[n][1] * inv0);
        *(float2*)&out[(size_t)(bb * SQ + s1row) * HID + ho*64 + col] =
            make_float2(o[n][2] * inv1, o[n][3] * inv1);
    }
}

// ---------------- host ----------------
extern "C" void kernel_launch(void* const* d_in, const int* in_sizes, int n_in,
                              void* d_out, int out_size) {
    const float* X    = (const float*)d_in[0];
    const float* mask = (const float*)d_in[1];

    ProjW pw;
    pw.w[0] = (const float*)d_in[2];  pw.b[0] = (const float*)d_in[3];   // wq, bq
    pw.w[1] = (const float*)d_in[4];  pw.b[1] = (const float*)d_in[5];   // wk, bk
    pw.w[2] = (const float*)d_in[6];  pw.b[2] = (const float*)d_in[7];   // wv, bv
    pw.w[3] = (const float*)d_in[8];  pw.b[3] = (const float*)d_in[9];   // wlq
    pw.w[4] = (const float*)d_in[10]; pw.b[4] = (const float*)d_in[11];  // wlk1
    pw.w[5] = (const float*)d_in[12]; pw.b[5] = (const float*)d_in[13];  // wlk2
    pw.w[6] = nullptr;                pw.b[6] = nullptr;                 // g_wsum/g_bsum

    sum_lv_weights<<<(HID*512 + 255)/256, 256>>>(
        (const float*)d_in[14], (const float*)d_in[16],
        (const float*)d_in[15], (const float*)d_in[17]);

    proj_tc<<<dim3(4, 32, 7), 256>>>(X, pw);
    gram_kernel<<<16, 256>>>();
    lqx_kernel<<<dim3(32, 16), 256>>>();

    const int smem = (2*64*KS2) * sizeof(float2) + (2*64*VS2) * sizeof(float); // 106,496 B
    cudaFuncSetAttribute(flash_tc3, cudaFuncAttributeMaxDynamicSharedMemorySize, smem);
    flash_tc3<<<dim3(32, 32), 128, smem>>>(mask, (float*)d_out);
}

// round 10
// speedup vs baseline: 1.0122x; 1.0122x over previous
#include <cuda_runtime.h>
#include <cuda_bf16.h>
#include <math.h>
#include <stdint.h>

// Problem constants
#define SQ   2048
#define HID  1024
#define DH   64
#define NHB  16
#define BHSD (NHB*SQ*DH)

// ---------------- scratch (static device memory; no allocation) ----------------
__device__ float g_V   [BHSD];
__device__ float g_LV  [BHSD];
__device__ float g_LQ  [BHSD];
__device__ float g_LK1 [BHSD];
__device__ float g_Mm  [NHB*64*64];
__device__ float g_wsum[HID*512];
__device__ float g_bsum[512];
// packed bf16 hi/lo pairs: .x = (hi[d],hi[d+1]), .y = (lo[d],lo[d+1])
// plane = branch*16 + (b*8+h): 0-15 global, 16-31 local
__device__ __align__(16) uint2 g_Qp [32*SQ*(DH/2)];   // [plane][s][dpair]
__device__ __align__(16) uint2 g_Kp [32*SQ*(DH/2)];   // [plane][s][dpair]
__device__ __align__(16) uint2 g_Vtp[32*DH*(SQ/2)];   // [plane][d][spair]

struct ProjW {
    const float* w[7];
    const float* b[7];
};

// ---------------- helpers ----------------
__device__ __forceinline__ float tf32_rna(float x) {
    uint32_t r; asm("cvt.rna.tf32.f32 %0, %1;" : "=r"(r) : "f"(x));
    return __uint_as_float(r);
}
__device__ __forceinline__ void mma8(float c[4],
        float a0, float a1, float a2, float a3, float b0, float b1) {
    uint32_t A0 = __float_as_uint(a0), A1 = __float_as_uint(a1),
             A2 = __float_as_uint(a2), A3 = __float_as_uint(a3),
             B0 = __float_as_uint(b0), B1 = __float_as_uint(b1);
    asm volatile(
        "mma.sync.aligned.m16n8k8.row.col.f32.tf32.tf32.f32 "
        "{%0,%1,%2,%3}, {%4,%5,%6,%7}, {%8,%9}, {%0,%1,%2,%3};"
        : "+f"(c[0]), "+f"(c[1]), "+f"(c[2]), "+f"(c[3])
        : "r"(A0), "r"(A1), "r"(A2), "r"(A3), "r"(B0), "r"(B1));
}
// bf16 m16n8k16 row.col, fp32 accumulate
__device__ __forceinline__ void mma16(float c[4], const uint32_t a[4],
                                      uint32_t b0, uint32_t b1) {
    asm volatile(
        "mma.sync.aligned.m16n8k16.row.col.f32.bf16.bf16.f32 "
        "{%0,%1,%2,%3}, {%4,%5,%6,%7}, {%8,%9}, {%0,%1,%2,%3};"
        : "+f"(c[0]), "+f"(c[1]), "+f"(c[2]), "+f"(c[3])
        : "r"(a[0]), "r"(a[1]), "r"(a[2]), "r"(a[3]), "r"(b0), "r"(b1));
}
__device__ __forceinline__ void cp16(uint32_t dst, const void* src) {
    asm volatile("cp.async.cg.shared.global [%0], [%1], 16;\n" :: "r"(dst), "l"(src));
}
__device__ __forceinline__ uint32_t pk2(__nv_bfloat16 a, __nv_bfloat16 b) {
    uint16_t xa = *reinterpret_cast<uint16_t*>(&a);
    uint16_t xb = *reinterpret_cast<uint16_t*>(&b);
    return (uint32_t)xa | ((uint32_t)xb << 16);
}
// pack (v0,v1) into interleaved hi/lo uint2
__device__ __forceinline__ uint2 pk_pair(float v0, float v1) {
    __nv_bfloat16 h0 = __float2bfloat16_rn(v0), h1 = __float2bfloat16_rn(v1);
    float l0 = v0 - __bfloat162float(h0), l1 = v1 - __bfloat162float(h1);
    return make_uint2(pk2(h0, h1),
                      pk2(__float2bfloat16_rn(l0), __float2bfloat16_rn(l1)));
}

// ---------------- kernel 0: fold wlv1+wlv2 ----------------
__global__ void sum_lv_weights(const float* __restrict__ w1, const float* __restrict__ w2,
                               const float* __restrict__ b1, const float* __restrict__ b2) {
    int i = blockIdx.x * blockDim.x + threadIdx.x;
    if (i < HID*512) g_wsum[i] = w1[i] + w2[i];
    if (i < 512)     g_bsum[i] = b1[i] + b2[i];
}

// ---------------- kernel 1: projection GEMM (3xTF32 legacy mma) ----------------
// pz: 0=Q->packed (x0.125), 1=K->packed, 2=V fp32, 3=LQ fp32, 4=LK1 fp32,
//     5=LK2->packed plane 16+, 6=LV fp32 (g_wsum/g_bsum)
#define XS_STRIDE 18
#define WS_STRIDE 132

__global__ __launch_bounds__(256) void proj_tc(const float* __restrict__ X, ProjW args) {
    const int pz = blockIdx.z;
    const float* __restrict__ W  = (pz == 6) ? g_wsum : args.w[pz];
    const float* __restrict__ Bv = (pz == 6) ? g_bsum : args.b[pz];

    const int n0 = blockIdx.x * 128;
    const int m0 = blockIdx.y * 128;

    __shared__ float2 Xs[128 * XS_STRIDE];
    __shared__ float2 Ws[16 * WS_STRIDE];

    const int tid  = threadIdx.x;
    const int w    = tid >> 5;
    const int lane = tid & 31;
    const int g    = lane >> 2;
    const int tg   = lane & 3;
    const int wm   = w & 3;
    const int wn   = w >> 2;

    float acc[2][8][4];
    #pragma unroll
    for (int mt = 0; mt < 2; mt++)
        #pragma unroll
        for (int n = 0; n < 8; n++)
            #pragma unroll
            for (int q = 0; q < 4; q++) acc[mt][n][q] = 0.f;

    float4 xr[2], wr[2];
    auto loadX = [&](int kb) {
        #pragma unroll
        for (int t = 0; t < 2; t++) {
            int i2 = tid + 256*t; int r = i2 >> 2, c = i2 & 3;
            xr[t] = *(const float4*)&X[(size_t)(m0 + r) * HID + kb + 4*c];
        }
    };
    auto loadW = [&](int kb) {
        #pragma unroll
        for (int t = 0; t < 2; t++) {
            int i2 = tid + 256*t; int r = i2 >> 5, c = i2 & 31;
            wr[t] = *(const float4*)&W[(size_t)(kb + r) * 512 + n0 + 4*c];
        }
    };

    loadX(0); loadW(0);

    for (int kb = 0; kb < HID; kb += 16) {
        __syncthreads();
        #pragma unroll
        for (int t = 0; t < 2; t++) {
            int i2 = tid + 256*t; int r = i2 >> 2, c = i2 & 3;
            float4 x = xr[t];
            float h0 = tf32_rna(x.x), h1 = tf32_rna(x.y), h2 = tf32_rna(x.z), h3 = tf32_rna(x.w);
            float4* p = (float4*)&Xs[r * XS_STRIDE + 4*c];
            p[0] = make_float4(h0, x.x - h0, h1, x.y - h1);
            p[1] = make_float4(h2, x.z - h2, h3, x.w - h3);
        }
        #pragma unroll
        for (int t = 0; t < 2; t++) {
            int i2 = tid + 256*t; int r = i2 >> 5, c = i2 & 31;
            float4 x = wr[t];
            float h0 = tf32_rna(x.x), h1 = tf32_rna(x.y), h2 = tf32_rna(x.z), h3 = tf32_rna(x.w);
            float4* p = (float4*)&Ws[r * WS_STRIDE + 4*c];
            p[0] = make_float4(h0, x.x - h0, h1, x.y - h1);
            p[1] = make_float4(h2, x.z - h2, h3, x.w - h3);
        }
        if (kb + 16 < HID) { loadX(kb + 16); loadW(kb + 16); }
        __syncthreads();

        #pragma unroll
        for (int kk = 0; kk < 2; kk++) {
            float2 a[2][4];
            #pragma unroll
            for (int mt = 0; mt < 2; mt++) {
                int r = 32*wm + 16*mt;
                a[mt][0] = Xs[(r + g    ) * XS_STRIDE + 8*kk + tg    ];
                a[mt][1] = Xs[(r + g + 8) * XS_STRIDE + 8*kk + tg    ];
                a[mt][2] = Xs[(r + g    ) * XS_STRIDE + 8*kk + tg + 4];
                a[mt][3] = Xs[(r + g + 8) * XS_STRIDE + 8*kk + tg + 4];
            }
            #pragma unroll
            for (int n = 0; n < 8; n++) {
                float2 b0 = Ws[(8*kk + tg    ) * WS_STRIDE + 64*wn + 8*n + g];
                float2 b1 = Ws[(8*kk + tg + 4) * WS_STRIDE + 64*wn + 8*n + g];
                #pragma unroll
                for (int mt = 0; mt < 2; mt++) {
                    mma8(acc[mt][n], a[mt][0].x, a[mt][1].x, a[mt][2].x, a[mt][3].x, b0.x, b1.x);
                    mma8(acc[mt][n], a[mt][0].x, a[mt][1].x, a[mt][2].x, a[mt][3].x, b0.y, b1.y);
                    mma8(acc[mt][n], a[mt][0].y, a[mt][1].y, a[mt][2].y, a[mt][3].y, b0.x, b1.x);
                }
            }
        }
    }

    // epilogue
    #pragma unroll
    for (int mt = 0; mt < 2; mt++) {
        #pragma unroll
        for (int n = 0; n < 8; n++) {
            int col = 64*wn + 8*n + 2*tg;
            int hh  = (n0 + col) >> 6;
            int d   = (n0 + col) & 63;      // even
            float b0 = Bv[n0 + col], b1 = Bv[n0 + col + 1];
            #pragma unroll
            for (int half = 0; half < 2; half++) {
                int m = m0 + 32*wm + 16*mt + g + 8*half;
                int bb = m >> 11, s = m & 2047;
                float v0 = acc[mt][n][2*half + 0] + b0;
                float v1 = acc[mt][n][2*half + 1] + b1;
                int cidx = bb*8 + hh;
                if (pz == 0) {
                    g_Qp[((size_t)cidx * SQ + s) * (DH/2) + (d>>1)] =
                        pk_pair(v0 * 0.125f, v1 * 0.125f);
                } else if (pz == 1) {
                    g_Kp[((size_t)cidx * SQ + s) * (DH/2) + (d>>1)] = pk_pair(v0, v1);
                } else if (pz == 5) {
                    g_Kp[((size_t)(16 + cidx) * SQ + s) * (DH/2) + (d>>1)] = pk_pair(v0, v1);
                } else {
                    float* Out = (pz == 2) ? g_V : (pz == 3) ? g_LQ
                               : (pz == 4) ? g_LK1 : g_LV;
                    *(float2*)&Out[((size_t)cidx * SQ + s) * DH + d] = make_float2(v0, v1);
                }
            }
        }
    }
}

// ---------------- kernel 2: Gram matrix G = LK1^T LK1 per (b,h) ----------------
__global__ __launch_bounds__(256) void gram_kernel() {
    const int bh = blockIdx.x;
    const float* __restrict__ P = g_LK1 + (size_t)bh * SQ * DH;
    __shared__ float T[32][65];
    const int tid = threadIdx.x;
    const int ty = tid >> 4, tx = tid & 15;

    float acc[4][4];
    #pragma unroll
    for (int i = 0; i < 4; i++)
        #pragma unroll
        for (int j = 0; j < 4; j++) acc[i][j] = 0.f;

    for (int s0 = 0; s0 < SQ; s0 += 32) {
        #pragma unroll
        for (int t = 0; t < 2; t++) {
            int idx = tid + t * 256;
            int r = idx >> 4, c = idx & 15;
            float4 v = *(const float4*)&P[(size_t)(s0 + r) * DH + 4*c];
            T[r][4*c+0] = v.x; T[r][4*c+1] = v.y; T[r][4*c+2] = v.z; T[r][4*c+3] = v.w;
        }
        __syncthreads();
        #pragma unroll 8
        for (int ss = 0; ss < 32; ss++) {
            float a_[4], b_[4];
            #pragma unroll
            for (int i = 0; i < 4; i++) a_[i] = T[ss][4*ty + i];
            #pragma unroll
            for (int j = 0; j < 4; j++) b_[j] = T[ss][4*tx + j];
            #pragma unroll
            for (int i = 0; i < 4; i++)
                #pragma unroll
                for (int j = 0; j < 4; j++) acc[i][j] += a_[i] * b_[j];
        }
        __syncthreads();
    }
    #pragma unroll
    for (int i = 0; i < 4; i++)
        #pragma unroll
        for (int j = 0; j < 4; j++)
            g_Mm[bh*4096 + (4*ty + i)*64 + (4*tx + j)] = acc[i][j];
}

// ---------------- kernel 3: LQ2 = (LQ @ G) * 0.125 -> packed plane 16+bh ----------------
__global__ __launch_bounds__(256) void lqx_kernel() {
    const int bh = blockIdx.y;
    const int r0 = blockIdx.x * 64;
    const float* __restrict__ Qp = g_LQ + (size_t)bh * SQ * DH;
    const float* __restrict__ Mp = g_Mm + bh * 4096;

    __shared__ float Msm[64*65];
    __shared__ float Qt[64*65];

    const int tid = threadIdx.x;

    #pragma unroll
    for (int t = 0; t < 4; t++) {
        int idx = tid + t * 256;
        int r = idx >> 4, c = idx & 15;
        float4 mv = *(const float4*)&Mp[r*64 + 4*c];
        Msm[r*65 + 4*c+0] = mv.x; Msm[r*65 + 4*c+1] = mv.y;
        Msm[r*65 + 4*c+2] = mv.z; Msm[r*65 + 4*c+3] = mv.w;
        float4 qv = *(const float4*)&Qp[(size_t)(r0 + r) * DH + 4*c];
        Qt[r*65 + 4*c+0] = qv.x; Qt[r*65 + 4*c+1] = qv.y;
        Qt[r*65 + 4*c+2] = qv.z; Qt[r*65 + 4*c+3] = qv.w;
    }
    __syncthreads();

    const int ty = tid >> 5;      // 0..7
    const int tx = tid & 31;      // col pair 2tx,2tx+1

    float acc[8][2];
    #pragma unroll
    for (int a = 0; a < 8; a++) { acc[a][0] = 0.f; acc[a][1] = 0.f; }

    #pragma unroll 4
    for (int k = 0; k < 64; k++) {
        float mb0 = Msm[k*65 + 2*tx], mb1 = Msm[k*65 + 2*tx + 1];
        #pragma unroll
        for (int a = 0; a < 8; a++) {
            float qa = Qt[(ty + 8*a)*65 + k];
            acc[a][0] += qa * mb0;
            acc[a][1] += qa * mb1;
        }
    }

    const int plane = 16 + bh;
    #pragma unroll
    for (int a = 0; a < 8; a++) {
        int row = r0 + ty + 8*a;
        g_Qp[((size_t)plane * SQ + row) * (DH/2) + tx] =
            pk_pair(acc[a][0] * 0.125f, acc[a][1] * 0.125f);
    }
}

// ---------------- kernel 3b: V transpose -> packed [plane][d][spair] ----------------
__global__ __launch_bounds__(256) void vtrans_kernel() {
    const int plane = blockIdx.y;
    const int s0 = blockIdx.x * 64;
    const float* __restrict__ src = (plane < 16)
        ? g_V  + (size_t)plane * SQ * DH
        : g_LV + (size_t)(plane - 16) * SQ * DH;
    __shared__ float T[64][65];
    const int tid = threadIdx.x;
    #pragma unroll
    for (int t = 0; t < 16; t++) {
        int idx = tid + 256*t;
        int sl = idx >> 6, d = idx & 63;
        T[d][sl] = src[(size_t)(s0 + sl) * DH + d];
    }
    __syncthreads();
    uint2* dst = g_Vtp + (size_t)plane * DH * (SQ/2);
    #pragma unroll
    for (int t = 0; t < 8; t++) {
        int idx = tid + 256*t;           // 0..2047
        int d = idx >> 5, sp = idx & 31;
        dst[(size_t)d * (SQ/2) + (s0 >> 1) + sp] = pk_pair(T[d][2*sp], T[d][2*sp + 1]);
    }
}

// ---------------- kernel 4: flash attention, bf16 m16n8k16 hi/lo pairs ----------------
// BR=64, BC=64, 128 threads = 4 warps. K/Vt staged as interleaved (hi,lo) uint2,
// row stride 36 uint2 (conflict-free per 16-lane phase). QK & PV both 3-term.
#define KSTR 36   // uint2 per staged row

__global__ __launch_bounds__(128, 2) void flash_bf(const float* __restrict__ mask,
                                                   float* __restrict__ out) {
    extern __shared__ uint2 smem2[];
    uint2* Kb0 = smem2;                // 64*KSTR
    uint2* Kb1 = Kb0 + 64*KSTR;
    uint2* Vb0 = Kb1 + 64*KSTR;
    uint2* Vb1 = Vb0 + 64*KSTR;

    const int rt = blockIdx.x;
    const int plane = blockIdx.y;
    const int branch = plane >> 4;
    const int cidx = plane & 15;
    const int bb = cidx >> 3;
    const int h  = cidx & 7;
    const int ho = branch ? (8 + h) : h;
    const bool domask = (branch == 0);

    const uint2* Qp  = g_Qp  + (size_t)plane * SQ * (DH/2);
    const uint2* Kp  = g_Kp  + (size_t)plane * SQ * (DH/2);
    const uint2* Vtp = g_Vtp + (size_t)plane * DH * (SQ/2);

    const int tid  = threadIdx.x;
    const int lane = tid & 31;
    const int g    = lane >> 2;
    const int tg   = lane & 3;
    const int r0   = 16 * (tid >> 5);

    const uint32_t kb0 = (uint32_t)__cvta_generic_to_shared(Kb0);
    const uint32_t kb1 = (uint32_t)__cvta_generic_to_shared(Kb1);
    const uint32_t vb0 = (uint32_t)__cvta_generic_to_shared(Vb0);
    const uint32_t vb1 = (uint32_t)__cvta_generic_to_shared(Vb1);

    auto stage = [&](int kt, int buf) {
        uint32_t kb = buf ? kb1 : kb0;
        uint32_t vb = buf ? vb1 : vb0;
        #pragma unroll
        for (int t = 0; t < 8; t++) {
            int idx = tid + 128*t;          // 0..1023
            int r = idx >> 4, c = idx & 15; // row, 16B chunk
            cp16(kb + (uint32_t)(r*KSTR*8 + c*16),
                 Kp + (size_t)(kt*64 + r) * (DH/2) + 2*c);
            cp16(vb + (uint32_t)(r*KSTR*8 + c*16),
                 Vtp + (size_t)r * (SQ/2) + kt*32 + 2*c);
        }
        asm volatile("cp.async.commit_group;\n");
    };

    // ---- Q fragments (packed hi/lo, register-resident) ----
    uint32_t qh[4][4], ql[4][4];
    #pragma unroll
    for (int kk = 0; kk < 4; kk++) {
        const uint2* qb = Qp + (size_t)(rt*64) * (DH/2);
        uint2 q00 = qb[(size_t)(r0 + g    ) * (DH/2) + 8*kk + tg    ];
        uint2 q10 = qb[(size_t)(r0 + g + 8) * (DH/2) + 8*kk + tg    ];
        uint2 q01 = qb[(size_t)(r0 + g    ) * (DH/2) + 8*kk + tg + 4];
        uint2 q11 = qb[(size_t)(r0 + g + 8) * (DH/2) + 8*kk + tg + 4];
        qh[kk][0] = q00.x; qh[kk][1] = q10.x; qh[kk][2] = q01.x; qh[kk][3] = q11.x;
        ql[kk][0] = q00.y; ql[kk][1] = q10.y; ql[kk][2] = q01.y; ql[kk][3] = q11.y;
    }

    float o[8][4];
    #pragma unroll
    for (int n = 0; n < 8; n++)
        #pragma unroll
        for (int q = 0; q < 4; q++) o[n][q] = 0.f;
    float m0r = -3.0e38f, m1r = -3.0e38f, l0r = 0.f, l1r = 0.f;

    stage(0, 0);

    for (int kt = 0; kt < 32; kt++) {
        if (kt + 1 < 32) {
            stage(kt + 1, (kt + 1) & 1);
            asm volatile("cp.async.wait_group 1;\n");
        } else {
            asm volatile("cp.async.wait_group 0;\n");
        }
        __syncthreads();
        const uint2* Ks = (kt & 1) ? Kb1 : Kb0;
        const uint2* Vs = (kt & 1) ? Vb1 : Vb0;

        // ---- S = Q K^T (3-term bf16-pair) ----
        float sv[8][4];
        #pragma unroll
        for (int n = 0; n < 8; n++)
            #pragma unroll
            for (int q = 0; q < 4; q++) sv[n][q] = 0.f;

        #pragma unroll
        for (int kk = 0; kk < 4; kk++) {
            #pragma unroll
            for (int n = 0; n < 8; n++) {
                uint2 b0 = Ks[(8*n + g) * KSTR + 8*kk + tg    ];
                uint2 b1 = Ks[(8*n + g) * KSTR + 8*kk + tg + 4];
                mma16(sv[n], qh[kk], b0.x, b1.x);
                mma16(sv[n], qh[kk], b0.y, b1.y);
                mma16(sv[n], ql[kk], b0.x, b1.x);
            }
        }

        if (domask) {
            #pragma unroll
            for (int n = 0; n < 8; n++) {
                float2 mm = __ldg((const float2*)&mask[(size_t)bb * SQ + kt*64 + 8*n + 2*tg]);
                sv[n][0] += mm.x; sv[n][1] += mm.y;
                sv[n][2] += mm.x; sv[n][3] += mm.y;
            }
        }

        // ---- online softmax (rows g and g+8; 4-lane groups share a row) ----
        float mt0 = sv[0][0], mt1 = sv[0][2];
        #pragma unroll
        for (int n = 0; n < 8; n++) {
            mt0 = fmaxf(mt0, fmaxf(sv[n][0], sv[n][1]));
            mt1 = fmaxf(mt1, fmaxf(sv[n][2], sv[n][3]));
        }
        mt0 = fmaxf(mt0, __shfl_xor_sync(0xffffffffu, mt0, 1));
        mt0 = fmaxf(mt0, __shfl_xor_sync(0xffffffffu, mt0, 2));
        mt1 = fmaxf(mt1, __shfl_xor_sync(0xffffffffu, mt1, 1));
        mt1 = fmaxf(mt1, __shfl_xor_sync(0xffffffffu, mt1, 2));

        float mn0 = fmaxf(m0r, mt0), mn1 = fmaxf(m1r, mt1);
        float c0 = __expf(m0r - mn0), c1 = __expf(m1r - mn1);
        float s0 = 0.f, s1 = 0.f;
        #pragma unroll
        for (int n = 0; n < 8; n++) {
            sv[n][0] = __expf(sv[n][0] - mn0); s0 += sv[n][0];
            sv[n][1] = __expf(sv[n][1] - mn0); s0 += sv[n][1];
            sv[n][2] = __expf(sv[n][2] - mn1); s1 += sv[n][2];
            sv[n][3] = __expf(sv[n][3] - mn1); s1 += sv[n][3];
        }
        s0 += __shfl_xor_sync(0xffffffffu, s0, 1);
        s0 += __shfl_xor_sync(0xffffffffu, s0, 2);
        s1 += __shfl_xor_sync(0xffffffffu, s1, 1);
        s1 += __shfl_xor_sync(0xffffffffu, s1, 2);
        l0r = l0r * c0 + s0; m0r = mn0;
        l1r = l1r * c1 + s1; m1r = mn1;
        #pragma unroll
        for (int n = 0; n < 8; n++) {
            o[n][0] *= c0; o[n][1] *= c0;
            o[n][2] *= c1; o[n][3] *= c1;
        }

        // ---- pack P into bf16 hi/lo A-fragments (pure local, no shuffles) ----
        uint32_t php[8][2], plp[8][2];
        #pragma unroll
        for (int n = 0; n < 8; n++) {
            __nv_bfloat16 h0 = __float2bfloat16_rn(sv[n][0]);
            __nv_bfloat16 h1 = __float2bfloat16_rn(sv[n][1]);
            __nv_bfloat16 h2 = __float2bfloat16_rn(sv[n][2]);
            __nv_bfloat16 h3 = __float2bfloat16_rn(sv[n][3]);
            php[n][0] = pk2(h0, h1);
            php[n][1] = pk2(h2, h3);
            float l0 = sv[n][0] - __bfloat162float(h0);
            float l1 = sv[n][1] - __bfloat162float(h1);
            float l2 = sv[n][2] - __bfloat162float(h2);
            float l3 = sv[n][3] - __bfloat162float(h3);
            plp[n][0] = pk2(__float2bfloat16_rn(l0), __float2bfloat16_rn(l1));
            plp[n][1] = pk2(__float2bfloat16_rn(l2), __float2bfloat16_rn(l3));
        }

        // ---- O += P V (3-term bf16-pair) ----
        #pragma unroll
        for (int c = 0; c < 4; c++) {
            uint32_t ah[4] = { php[2*c][0], php[2*c][1], php[2*c+1][0], php[2*c+1][1] };
            uint32_t al[4] = { plp[2*c][0], plp[2*c][1], plp[2*c+1][0], plp[2*c+1][1] };
            #pragma unroll
            for (int n = 0; n < 8; n++) {
                uint2 b0 = Vs[(8*n + g) * KSTR + 8*c + tg    ];
                uint2 b1 = Vs[(8*n + g) * KSTR + 8*c + tg + 4];
                mma16(o[n], ah, b0.x, b1.x);
                mma16(o[n], ah, b0.y, b1.y);
                mma16(o[n], al, b0.x, b1.x);
            }
        }
        __syncthreads();
    }

    // ---- epilogue ----
    float inv0 = 1.0f / l0r, inv1 = 1.0f / l1r;
    int s0row = rt*64 + r0 + g;
    int s1row = s0row + 8;
    #pragma unroll
    for (int n = 0; n < 8; n++) {
        int col = 8*n + 2*tg;
        *(float2*)&out[(size_t)(bb * SQ + s0row) * HID + ho*64 + col] =
            make_float2(o[n][0] * inv0, o[n][1] * inv0);
        *(float2*)&out[(size_t)(bb * SQ + s1row) * HID + ho*64 + col] =
            make_float2(o[n][2] * inv1, o[n][3] * inv1);
    }
}

// ---------------- host ----------------
extern "C" void kernel_launch(void* const* d_in, const int* in_sizes, int n_in,
                              void* d_out, int out_size) {
    const float* X    = (const float*)d_in[0];
    const float* mask = (const float*)d_in[1];

    ProjW pw;
    pw.w[0] = (const float*)d_in[2];  pw.b[0] = (const float*)d_in[3];   // wq, bq
    pw.w[1] = (const float*)d_in[4];  pw.b[1] = (const float*)d_in[5];   // wk, bk
    pw.w[2] = (const float*)d_in[6];  pw.b[2] = (const float*)d_in[7];   // wv, bv
    pw.w[3] = (const float*)d_in[8];  pw.b[3] = (const float*)d_in[9];   // wlq
    pw.w[4] = (const float*)d_in[10]; pw.b[4] = (const float*)d_in[11];  // wlk1
    pw.w[5] = (const float*)d_in[12]; pw.b[5] = (const float*)d_in[13];  // wlk2
    pw.w[6] = nullptr;                pw.b[6] = nullptr;                 // g_wsum/g_bsum

    sum_lv_weights<<<(HID*512 + 255)/256, 256>>>(
        (const float*)d_in[14], (const float*)d_in[16],
        (const float*)d_in[15], (const float*)d_in[17]);

    proj_tc<<<dim3(4, 32, 7), 256>>>(X, pw);
    gram_kernel<<<16, 256>>>();
    lqx_kernel<<<dim3(32, 16), 256>>>();
    vtrans_kernel<<<dim3(32, 32), 256>>>();

    const int smem = 4 * 64 * KSTR * sizeof(uint2);   // 73,728 B
    cudaFuncSetAttribute(flash_bf, cudaFuncAttributeMaxDynamicSharedMemorySize, smem);
    flash_bf<<<dim3(32, 32), 128, smem>>>(mask, (float*)d_out);
}